// round 14
// baseline (speedup 1.0000x reference)
#include <cuda_runtime.h>
#include <cuda_fp16.h>
#include <cuda_bf16.h>
#include <cstdint>

// ---------------- problem constants ----------------
#define D_MODEL 1024
#define NHEAD   16
#define D_HEAD  64
#define D_FF    4096
#define BATCH   2
#define SEQ     2048
#define NTOK    (BATCH * SEQ)       // 4096 tokens
#define QKVS    3072                // fused QKV row stride
#define EPS     1e-5f

// ---------------- scratch (no allocations allowed) ----------------
__device__ __half g_xh   [NTOK * D_MODEL];
__device__ __half g_Wqkvh[QKVS * D_MODEL];     // rows: 0..1023 Wq, 1024.. Wk, 2048.. Wv
__device__ float  g_bqkv [QKVS];
__device__ __half g_Woh  [D_MODEL * D_MODEL];
__device__ __half g_W1h  [D_FF * D_MODEL];
__device__ __half g_W2h  [D_MODEL * D_FF];
__device__ __half g_qkvh [NTOK * QKVS];        // fused QKV activations
__device__ __half g_atth [NTOK * D_MODEL];
__device__ __half g_hh   [NTOK * D_MODEL];
__device__ __half g_ffh  [NTOK * D_FF];
__device__ float  g_tmp  [NTOK * D_MODEL];     // attn_proj, then ffn2 out
__device__ float  g_h    [NTOK * D_MODEL];     // LN1 output (fp32 residual)

// =======================================================================
// PTX helpers (plain sm_103-compatible: mma.sync / ldmatrix / cp.async)
// =======================================================================
__device__ __forceinline__ uint32_t smem_u32(const void* p) {
    uint32_t a;
    asm("{ .reg .u64 t; cvta.to.shared.u64 t, %1; cvt.u32.u64 %0, t; }"
        : "=r"(a) : "l"(p));
    return a;
}

__device__ __forceinline__ void mma16816(float* d, const uint32_t* a, const uint32_t* b) {
    asm volatile(
        "mma.sync.aligned.m16n8k16.row.col.f32.f16.f16.f32 "
        "{%0,%1,%2,%3}, {%4,%5,%6,%7}, {%8,%9}, {%0,%1,%2,%3};"
        : "+f"(d[0]), "+f"(d[1]), "+f"(d[2]), "+f"(d[3])
        : "r"(a[0]), "r"(a[1]), "r"(a[2]), "r"(a[3]), "r"(b[0]), "r"(b[1]));
}

#define LDMX4(r0, r1, r2, r3, addr)                                         \
    asm volatile("ldmatrix.sync.aligned.m8n8.x4.shared.b16 "                \
                 "{%0,%1,%2,%3}, [%4];"                                     \
                 : "=r"(r0), "=r"(r1), "=r"(r2), "=r"(r3) : "r"(addr))

#define LDMX4T(r0, r1, r2, r3, addr)                                        \
    asm volatile("ldmatrix.sync.aligned.m8n8.x4.trans.shared.b16 "          \
                 "{%0,%1,%2,%3}, [%4];"                                     \
                 : "=r"(r0), "=r"(r1), "=r"(r2), "=r"(r3) : "r"(addr))

#define CP_ASYNC16(saddr, gaddr)                                            \
    asm volatile("cp.async.cg.shared.global [%0], [%1], 16;"                \
                 :: "r"(saddr), "l"(gaddr) : "memory")
#define CP_COMMIT() asm volatile("cp.async.commit_group;" ::: "memory")
#define CP_WAIT(n)  asm volatile("cp.async.wait_group %0;" :: "n"(n) : "memory")

__device__ __forceinline__ uint32_t pack_h2(float lo, float hi) {
    __half2 h = __float22half2_rn(make_float2(lo, hi));
    return *(uint32_t*)&h;
}

// =======================================================================
// Fused fp32 -> fp16 conversion for all weight/act tensors in ONE launch.
// =======================================================================
struct F2HArgs {
    const float4 *s0, *s1, *s2, *s3, *s4, *s5, *s6;
    uint2        *d0, *d1, *d2, *d3, *d4, *d5, *d6;
    const float *bq, *bk, *bv;
    float *bqkv;
};

__global__ __launch_bounds__(256)
void f2h_all(F2HArgs a)
{
    const int i = blockIdx.x * 256 + threadIdx.x;    // < 16 * 2^18
    const int unit = i >> 18;
    const float4* s; uint2* d; int off;
    if      (unit <  4) { s = a.s0; d = a.d0; off = i;              }
    else if (unit == 4) { s = a.s1; d = a.d1; off = i - (4  << 18); }
    else if (unit == 5) { s = a.s2; d = a.d2; off = i - (5  << 18); }
    else if (unit == 6) { s = a.s3; d = a.d3; off = i - (6  << 18); }
    else if (unit == 7) { s = a.s4; d = a.d4; off = i - (7  << 18); }
    else if (unit < 12) { s = a.s5; d = a.d5; off = i - (8  << 18); }
    else                { s = a.s6; d = a.d6; off = i - (12 << 18); }
    const float4 v = s[off];
    uint2 o;
    o.x = pack_h2(v.x, v.y);
    o.y = pack_h2(v.z, v.w);
    d[off] = o;

    if (blockIdx.x == 0) {
#pragma unroll
        for (int r = 0; r < 4; r++) {
            const int c = threadIdx.x + r * 256;
            a.bqkv[c]        = a.bq[c];
            a.bqkv[c + 1024] = a.bk[c];
            a.bqkv[c + 2048] = a.bv[c];
        }
    }
}

// =======================================================================
// fp16 HMMA GEMM: C[M,N] = A[M,K] @ W[N,K]^T + bias[N]
// CTA 128x128, BK=64, 128 threads = 4 warps (2Mx2N), warp tile 64x64.
// 2-stage cp.async pipeline, SINGLE fragment set (160 hot regs) ->
// fits 3 CTAs/SM (12 warps, 3/scheduler) for TLP latency hiding.
// SMEM rows padded to 72 halfs (144B): ldmatrix conflict-free.
// =======================================================================
#define LDSH   72
#define GSTG   2
#define TILE_B (128 * LDSH * 2)           // 18432 B per matrix per stage
#define GSMEM  (2 * GSTG * TILE_B)        // 73728 B

template <bool RELU, bool HALF_OUT>
__global__ __launch_bounds__(128, 3)
void gemm_h(const __half* __restrict__ A, const __half* __restrict__ W,
            const float* __restrict__ bias, void* __restrict__ Cout,
            int M, int N, int K)
{
    extern __shared__ __align__(16) char dsm[];
    const uint32_t smemA = smem_u32(dsm);
    const uint32_t smemW = smemA + GSTG * TILE_B;

    const int tid  = threadIdx.x;
    const int wid  = tid >> 5;
    const int lane = tid & 31;
    const int wm   = wid >> 1;         // 2 -> 64 M-rows each
    const int wn   = wid & 1;          // 2 -> 64 N-cols each
    const int g    = lane >> 2;
    const int t4   = lane & 3;

    const int bm = blockIdx.y * 128;
    const int bn = blockIdx.x * 128;

    float acc[4][8][4];
#pragma unroll
    for (int i = 0; i < 4; i++)
#pragma unroll
        for (int j = 0; j < 8; j++)
#pragma unroll
            for (int c = 0; c < 4; c++) acc[i][j][c] = 0.f;

    // cp.async: 1024 16B-chunks per matrix per stage (128 rows x 8), 8/thread
#define ISSUE_G(t, s)                                                           \
    do {                                                                        \
        const uint32_t sa = smemA + (s) * TILE_B;                               \
        const uint32_t sw = smemW + (s) * TILE_B;                               \
        _Pragma("unroll")                                                       \
        for (int sl = 0; sl < 8; sl++) {                                        \
            const int idx = tid + sl * 128;                                     \
            const int row = idx >> 3, c16 = idx & 7;                            \
            CP_ASYNC16(sa + (uint32_t)((row * LDSH + c16 * 8) * 2),             \
                       A + (size_t)(bm + row) * K + (t) * 64 + c16 * 8);        \
        }                                                                       \
        _Pragma("unroll")                                                       \
        for (int sl = 0; sl < 8; sl++) {                                        \
            const int idx = tid + sl * 128;                                     \
            const int row = idx >> 3, c16 = idx & 7;                            \
            CP_ASYNC16(sw + (uint32_t)((row * LDSH + c16 * 8) * 2),             \
                       W + (size_t)(bn + row) * K + (t) * 64 + c16 * 8);        \
        }                                                                       \
    } while (0)

    // ldmatrix byte offsets within one stage
    const int r7   = lane & 7;
    const int rsel = (lane >> 3) & 1;
    const int hsel = lane >> 4;
    const uint32_t offA0 = (uint32_t)((wm * 64 + r7 + rsel * 8) * (LDSH * 2) + hsel * 16);
    const uint32_t offB0 = (uint32_t)((wn * 64 + r7 + hsel * 8) * (LDSH * 2) + rsel * 16);

    // single fragment set (keeps regs <= 170 for 3 CTAs/SM)
    uint32_t af[4][4], bf[8][2];

#define LOAD_FRAG(stage, ks)                                                    \
    do {                                                                        \
        const uint32_t ab_ = smemA + (uint32_t)((stage) * TILE_B) + offA0 + (ks) * 32; \
        const uint32_t bb_ = smemW + (uint32_t)((stage) * TILE_B) + offB0 + (ks) * 32; \
        _Pragma("unroll")                                                       \
        for (int i = 0; i < 4; i++)                                             \
            LDMX4(af[i][0], af[i][1], af[i][2], af[i][3],                       \
                  ab_ + (uint32_t)(i * 16 * LDSH * 2));                         \
        _Pragma("unroll")                                                       \
        for (int jp = 0; jp < 4; jp++)                                          \
            LDMX4(bf[2 * jp][0], bf[2 * jp][1], bf[2 * jp + 1][0], bf[2 * jp + 1][1], \
                  bb_ + (uint32_t)(jp * 16 * LDSH * 2));                        \
    } while (0)

#define MMA_SET()                                                               \
    do {                                                                        \
        _Pragma("unroll")                                                       \
        for (int i = 0; i < 4; i++)                                             \
            _Pragma("unroll")                                                   \
            for (int j = 0; j < 8; j++)                                         \
                mma16816(acc[i][j], af[i], bf[j]);                              \
    } while (0)

    const int NT = K / 64;

    // prologue: both stages in flight; stage 0 confirmed
    ISSUE_G(0, 0); CP_COMMIT();
    ISSUE_G(1, 1); CP_COMMIT();
    CP_WAIT(1);
    __syncthreads();

    for (int t = 0; t < NT; ++t) {
        const int st = t & 1;
#pragma unroll
        for (int ks = 0; ks < 4; ks++) {
            LOAD_FRAG(st, ks);
            MMA_SET();
        }
        if (t + 1 < NT) {
            CP_WAIT(0);                    // stage t+1 landed
            __syncthreads();               // all reads of buffer st done
            if (t + 2 < NT) {              // refill freed buffer st
                ISSUE_G(t + 2, st);
                CP_COMMIT();
            }
        }
    }

    // ---- epilogue ----
#pragma unroll
    for (int j = 0; j < 8; j++) {
        const int col = bn + wn * 64 + j * 8 + t4 * 2;
        const float b0 = bias[col];
        const float b1 = bias[col + 1];
#pragma unroll
        for (int i = 0; i < 4; i++) {
            const int r0 = bm + wm * 64 + i * 16 + g;
            float v00 = acc[i][j][0] + b0, v01 = acc[i][j][1] + b1;
            float v10 = acc[i][j][2] + b0, v11 = acc[i][j][3] + b1;
            if (RELU) {
                v00 = fmaxf(v00, 0.f); v01 = fmaxf(v01, 0.f);
                v10 = fmaxf(v10, 0.f); v11 = fmaxf(v11, 0.f);
            }
            if (HALF_OUT) {
                __half* C = (__half*)Cout;
                *(__half2*)(C + (size_t)r0 * N + col)       = __float22half2_rn(make_float2(v00, v01));
                *(__half2*)(C + (size_t)(r0 + 8) * N + col) = __float22half2_rn(make_float2(v10, v11));
            } else {
                float* C = (float*)Cout;
                *(float2*)(C + (size_t)r0 * N + col)       = make_float2(v00, v01);
                *(float2*)(C + (size_t)(r0 + 8) * N + col) = make_float2(v10, v11);
            }
        }
    }
#undef ISSUE_G
#undef LOAD_FRAG
#undef MMA_SET
}

// =======================================================================
// fp16 HMMA flash attention over the fused QKV buffer (unchanged).
// =======================================================================
#define ATS 72

__global__ __launch_bounds__(256)
void flash16(const __half* __restrict__ QKV, __half* __restrict__ O)
{
    __shared__ __half Qs[128 * ATS];
    __shared__ __half Ks[2][64 * ATS];
    __shared__ __half Vs[2][64 * ATS];

    const int tid  = threadIdx.x;
    const int w    = tid >> 5;
    const int lane = tid & 31;
    const int g    = lane >> 2;
    const int t4   = lane & 3;
    const int bh   = blockIdx.y;
    const int b    = bh >> 4;
    const int h    = bh & 15;
    const int q0   = blockIdx.x * 128;
    const int m    = w * 16;

    const size_t baseQ = (size_t)b * SEQ * QKVS + (size_t)h * D_HEAD;
    const size_t baseK = baseQ + 1024;
    const size_t baseV = baseQ + 2048;
    const size_t baseO = (size_t)b * SEQ * D_MODEL + (size_t)h * D_HEAD;

    // ---- load Q tile (128 rows, scaled by 0.125) ----
    const __half2 sc = __float2half2_rn(0.125f);
#pragma unroll
    for (int s = 0; s < 4; s++) {
        int slot = tid + s * 256;          // 0..1023
        int row  = slot >> 3;              // 0..127
        int c8   = (slot & 7) * 8;
        uint4 v = *(const uint4*)(QKV + baseQ + (size_t)(q0 + row) * QKVS + c8);
        __half2* hv = (__half2*)&v;
        hv[0] = __hmul2(hv[0], sc); hv[1] = __hmul2(hv[1], sc);
        hv[2] = __hmul2(hv[2], sc); hv[3] = __hmul2(hv[3], sc);
        *(uint4*)&Qs[row * ATS + c8] = v;
    }
    __syncthreads();

    const int r7   = lane & 7;
    const int rsel = (lane >> 3) & 1;
    const int hsel = lane >> 4;

    uint32_t qf[4][4];
    {
        const uint32_t qb = smem_u32(Qs) +
            (uint32_t)((m + r7 + rsel * 8) * (ATS * 2) + hsel * 16);
#pragma unroll
        for (int ks = 0; ks < 4; ks++)
            LDMX4(qf[ks][0], qf[ks][1], qf[ks][2], qf[ks][3], qb + ks * 32);
    }

    const uint32_t offK0 = (uint32_t)((r7 + hsel * 8) * (ATS * 2) + rsel * 16);
    const uint32_t offV0 = (uint32_t)((rsel * 8 + r7) * (ATS * 2) + hsel * 16);
    const uint32_t kBase[2] = { smem_u32(Ks[0]), smem_u32(Ks[1]) };
    const uint32_t vBase[2] = { smem_u32(Vs[0]), smem_u32(Vs[1]) };

#define ISSUE_TILE(kt, buf)                                                     \
    do {                                                                        \
        _Pragma("unroll")                                                       \
        for (int s = 0; s < 2; s++) {                                           \
            int slot = tid + s * 256;      /* 0..511 */                         \
            int row  = slot >> 3;          /* 0..63 */                          \
            int c8   = (slot & 7) * 8;                                          \
            const size_t ro = (size_t)((kt) * 64 + row) * QKVS + c8;            \
            uint32_t so = (uint32_t)((row * ATS + c8) * 2);                     \
            CP_ASYNC16(kBase[buf] + so, QKV + baseK + ro);                      \
            CP_ASYNC16(vBase[buf] + so, QKV + baseV + ro);                      \
        }                                                                       \
        CP_COMMIT();                                                            \
    } while (0)

    float o[8][4];
#pragma unroll
    for (int j = 0; j < 8; j++)
#pragma unroll
        for (int c = 0; c < 4; c++) o[j][c] = 0.f;
    float m0 = -1e30f, m1 = -1e30f, l0 = 0.f, l1 = 0.f;

    ISSUE_TILE(0, 0);

    const int NKT = SEQ / 64;
    for (int kt = 0; kt < NKT; ++kt) {
        const int buf = kt & 1;
        if (kt + 1 < NKT) { ISSUE_TILE(kt + 1, buf ^ 1); CP_WAIT(1); }
        else              { CP_WAIT(0); }
        __syncthreads();

        // ---- S = (Q/8) K^T ----
        float s_[8][4];
#pragma unroll
        for (int j = 0; j < 8; j++)
#pragma unroll
            for (int c = 0; c < 4; c++) s_[j][c] = 0.f;

        const uint32_t kb = kBase[buf] + offK0;
#pragma unroll
        for (int ks = 0; ks < 4; ks++) {
            uint32_t bfk[8][2];
#pragma unroll
            for (int jp = 0; jp < 4; jp++)
                LDMX4(bfk[2 * jp][0], bfk[2 * jp][1], bfk[2 * jp + 1][0], bfk[2 * jp + 1][1],
                      kb + (uint32_t)(jp * 16 * ATS * 2 + ks * 32));
#pragma unroll
            for (int j = 0; j < 8; j++)
                mma16816(s_[j], qf[ks], bfk[j]);
        }

        // ---- online softmax ----
        float mx0 = -1e30f, mx1 = -1e30f;
#pragma unroll
        for (int j = 0; j < 8; j++) {
            mx0 = fmaxf(mx0, fmaxf(s_[j][0], s_[j][1]));
            mx1 = fmaxf(mx1, fmaxf(s_[j][2], s_[j][3]));
        }
        mx0 = fmaxf(mx0, __shfl_xor_sync(0xffffffffu, mx0, 1));
        mx0 = fmaxf(mx0, __shfl_xor_sync(0xffffffffu, mx0, 2));
        mx1 = fmaxf(mx1, __shfl_xor_sync(0xffffffffu, mx1, 1));
        mx1 = fmaxf(mx1, __shfl_xor_sync(0xffffffffu, mx1, 2));

        const float nm0 = fmaxf(m0, mx0);
        const float nm1 = fmaxf(m1, mx1);
        const float cr0 = __expf(m0 - nm0);
        const float cr1 = __expf(m1 - nm1);
        m0 = nm0; m1 = nm1;

        float ps0 = 0.f, ps1 = 0.f;
#pragma unroll
        for (int j = 0; j < 8; j++) {
            s_[j][0] = __expf(s_[j][0] - m0);
            s_[j][1] = __expf(s_[j][1] - m0);
            s_[j][2] = __expf(s_[j][2] - m1);
            s_[j][3] = __expf(s_[j][3] - m1);
            ps0 += s_[j][0] + s_[j][1];
            ps1 += s_[j][2] + s_[j][3];
        }
        ps0 += __shfl_xor_sync(0xffffffffu, ps0, 1);
        ps0 += __shfl_xor_sync(0xffffffffu, ps0, 2);
        ps1 += __shfl_xor_sync(0xffffffffu, ps1, 1);
        ps1 += __shfl_xor_sync(0xffffffffu, ps1, 2);
        l0 = l0 * cr0 + ps0;
        l1 = l1 * cr1 + ps1;

#pragma unroll
        for (int j = 0; j < 8; j++) {
            o[j][0] *= cr0; o[j][1] *= cr0;
            o[j][2] *= cr1; o[j][3] *= cr1;
        }

        // ---- O += P V ----
        const uint32_t vb = vBase[buf] + offV0;
#pragma unroll
        for (int ks = 0; ks < 4; ks++) {
            uint32_t pa[4];
            pa[0] = pack_h2(s_[2 * ks][0],     s_[2 * ks][1]);
            pa[1] = pack_h2(s_[2 * ks][2],     s_[2 * ks][3]);
            pa[2] = pack_h2(s_[2 * ks + 1][0], s_[2 * ks + 1][1]);
            pa[3] = pack_h2(s_[2 * ks + 1][2], s_[2 * ks + 1][3]);

            uint32_t bfv[8][2];
#pragma unroll
            for (int jp = 0; jp < 4; jp++)
                LDMX4T(bfv[2 * jp][0], bfv[2 * jp][1], bfv[2 * jp + 1][0], bfv[2 * jp + 1][1],
                       vb + (uint32_t)(ks * 16 * ATS * 2 + jp * 32));
#pragma unroll
            for (int j = 0; j < 8; j++)
                mma16816(o[j], pa, bfv[j]);
        }
        __syncthreads();
    }

    // ---- finalize + store (half) ----
    const float inv0 = 1.f / l0;
    const float inv1 = 1.f / l1;
    const int row0 = q0 + m + g;
    const int row1 = row0 + 8;
#pragma unroll
    for (int j = 0; j < 8; j++) {
        const int col = j * 8 + t4 * 2;
        *(__half2*)(O + baseO + (size_t)row0 * D_MODEL + col) =
            __float22half2_rn(make_float2(o[j][0] * inv0, o[j][1] * inv0));
        *(__half2*)(O + baseO + (size_t)row1 * D_MODEL + col) =
            __float22half2_rn(make_float2(o[j][2] * inv1, o[j][3] * inv1));
    }
#undef ISSUE_TILE
}

// =======================================================================
// Fused residual add + LayerNorm; optional extra half output.
// =======================================================================
__device__ __forceinline__ float block_sum(float v, float* red)
{
    for (int o = 16; o; o >>= 1) v += __shfl_down_sync(0xffffffffu, v, o);
    if ((threadIdx.x & 31) == 0) red[threadIdx.x >> 5] = v;
    __syncthreads();
    if (threadIdx.x < 8) {
        v = red[threadIdx.x];
        for (int o = 4; o; o >>= 1) v += __shfl_down_sync(0xffu, v, o);
        if (threadIdx.x == 0) red[0] = v;
    }
    __syncthreads();
    float r = red[0];
    __syncthreads();
    return r;
}

template <bool WRITE_HALF>
__global__ __launch_bounds__(256)
void add_ln_kernel(const float* __restrict__ X,
                   const float* __restrict__ Y,
                   const float* __restrict__ g,
                   const float* __restrict__ be,
                   float* __restrict__ out,
                   __half* __restrict__ outh)
{
    __shared__ float red[8];
    const int row = blockIdx.x;
    const int tid = threadIdx.x;
    const float* xr = X + (size_t)row * D_MODEL;
    const float* yr = Y + (size_t)row * D_MODEL;

    float vals[4];
    float sum = 0.f;
#pragma unroll
    for (int i = 0; i < 4; i++) {
        int c = tid + i * 256;
        vals[i] = xr[c] + yr[c];
        sum += vals[i];
    }
    float mu = block_sum(sum, red) * (1.f / D_MODEL);

    float vsum = 0.f;
#pragma unroll
    for (int i = 0; i < 4; i++) {
        float d = vals[i] - mu;
        vsum += d * d;
    }
    float var = block_sum(vsum, red) * (1.f / D_MODEL);
    float rstd = rsqrtf(var + EPS);

    float* orow = out + (size_t)row * D_MODEL;
    __half* hrow = WRITE_HALF ? outh + (size_t)row * D_MODEL : nullptr;
#pragma unroll
    for (int i = 0; i < 4; i++) {
        int c = tid + i * 256;
        float r = (vals[i] - mu) * rstd * g[c] + be[c];
        orow[c] = r;
        if (WRITE_HALF) hrow[c] = __float2half(r);
    }
}

// =======================================================================
// kernel_launch
// input order: x, Wq, bq, Wk, bk, Wv, bv, Wo, bo, W1, b1, W2, b2, g1, be1, g2, be2
// =======================================================================
extern "C" void kernel_launch(void* const* d_in, const int* in_sizes, int n_in,
                              void* d_out, int out_size)
{
    const float* x   = (const float*)d_in[0];
    const float* Wq  = (const float*)d_in[1];
    const float* bq  = (const float*)d_in[2];
    const float* Wk  = (const float*)d_in[3];
    const float* bk  = (const float*)d_in[4];
    const float* Wv  = (const float*)d_in[5];
    const float* bv  = (const float*)d_in[6];
    const float* Wo  = (const float*)d_in[7];
    const float* bo  = (const float*)d_in[8];
    const float* W1  = (const float*)d_in[9];
    const float* b1  = (const float*)d_in[10];
    const float* W2  = (const float*)d_in[11];
    const float* b2  = (const float*)d_in[12];
    const float* g1  = (const float*)d_in[13];
    const float* be1 = (const float*)d_in[14];
    const float* g2  = (const float*)d_in[15];
    const float* be2 = (const float*)d_in[16];
    float* out = (float*)d_out;

    __half *xh, *Wqkvh, *Woh, *W1h, *W2h, *qkvh, *atth, *hh, *ffh;
    float *bqkv, *tmp, *h;
    cudaGetSymbolAddress((void**)&xh,    g_xh);
    cudaGetSymbolAddress((void**)&Wqkvh, g_Wqkvh);
    cudaGetSymbolAddress((void**)&bqkv,  g_bqkv);
    cudaGetSymbolAddress((void**)&Woh,   g_Woh);
    cudaGetSymbolAddress((void**)&W1h,   g_W1h);
    cudaGetSymbolAddress((void**)&W2h,   g_W2h);
    cudaGetSymbolAddress((void**)&qkvh,  g_qkvh);
    cudaGetSymbolAddress((void**)&atth,  g_atth);
    cudaGetSymbolAddress((void**)&hh,    g_hh);
    cudaGetSymbolAddress((void**)&ffh,   g_ffh);
    cudaGetSymbolAddress((void**)&tmp,   g_tmp);
    cudaGetSymbolAddress((void**)&h,     g_h);

    cudaFuncSetAttribute(gemm_h<false, true >, cudaFuncAttributeMaxDynamicSharedMemorySize, GSMEM);
    cudaFuncSetAttribute(gemm_h<false, false>, cudaFuncAttributeMaxDynamicSharedMemorySize, GSMEM);
    cudaFuncSetAttribute(gemm_h<true,  true >, cudaFuncAttributeMaxDynamicSharedMemorySize, GSMEM);

    // ---- fused conversions + bias concat (single launch) ----
    F2HArgs fa;
    fa.s0 = (const float4*)x;  fa.d0 = (uint2*)xh;
    fa.s1 = (const float4*)Wq; fa.d1 = (uint2*)Wqkvh;                       // rows 0..1023
    fa.s2 = (const float4*)Wk; fa.d2 = (uint2*)(Wqkvh + 1024 * D_MODEL);    // rows 1024..
    fa.s3 = (const float4*)Wv; fa.d3 = (uint2*)(Wqkvh + 2048 * D_MODEL);    // rows 2048..
    fa.s4 = (const float4*)Wo; fa.d4 = (uint2*)Woh;
    fa.s5 = (const float4*)W1; fa.d5 = (uint2*)W1h;
    fa.s6 = (const float4*)W2; fa.d6 = (uint2*)W2h;
    fa.bq = bq; fa.bk = bk; fa.bv = bv; fa.bqkv = bqkv;
    f2h_all<<<(16 << 18) / 256, 256>>>(fa);

    const dim3 gQKV(QKVS / 128,    NTOK / 128);   // (24, 32)
    const dim3 gDxD(D_MODEL / 128, NTOK / 128);   // (8, 32)
    const dim3 gFF1(D_FF / 128,    NTOK / 128);   // (32, 32)

    // fused QKV projection -> half [NTOK][3072]
    gemm_h<false, true><<<gQKV, 128, GSMEM>>>(xh, Wqkvh, bqkv, qkvh, NTOK, QKVS, D_MODEL);

    // attention -> half
    flash16<<<dim3(SEQ / 128, BATCH * NHEAD), 256>>>(qkvh, atth);

    // output projection (fp32 out) + LN1 (fp32 + half out)
    gemm_h<false, false><<<gDxD, 128, GSMEM>>>(atth, Woh, bo, tmp, NTOK, D_MODEL, D_MODEL);
    add_ln_kernel<true><<<NTOK, 256>>>(x, tmp, g1, be1, h, hh);

    // FFN
    gemm_h<true,  true ><<<gFF1, 128, GSMEM>>>(hh,  W1h, b1, ffh, NTOK, D_FF, D_MODEL);
    gemm_h<false, false><<<gDxD, 128, GSMEM>>>(ffh, W2h, b2, tmp, NTOK, D_MODEL, D_FF);

    // LN2 -> output
    add_ln_kernel<false><<<NTOK, 256>>>(h, tmp, g2, be2, out, nullptr);
}

// round 16
// speedup vs baseline: 1.0764x; 1.0764x over previous
#include <cuda_runtime.h>
#include <cuda_fp16.h>
#include <cuda_bf16.h>
#include <cstdint>

// ---------------- problem constants ----------------
#define D_MODEL 1024
#define NHEAD   16
#define D_HEAD  64
#define D_FF    4096
#define BATCH   2
#define SEQ     2048
#define NTOK    (BATCH * SEQ)       // 4096 tokens
#define QKVS    3072                // fused QKV row stride
#define EPS     1e-5f

// ---------------- scratch (no allocations allowed) ----------------
__device__ __half g_xh   [NTOK * D_MODEL];
__device__ __half g_Wqkvh[QKVS * D_MODEL];     // rows: 0..1023 Wq, 1024.. Wk, 2048.. Wv
__device__ float  g_bqkv [QKVS];
__device__ __half g_Woh  [D_MODEL * D_MODEL];
__device__ __half g_W1h  [D_FF * D_MODEL];
__device__ __half g_W2h  [D_MODEL * D_FF];
__device__ __half g_qkvh [NTOK * QKVS];        // fused QKV activations
__device__ __half g_atth [NTOK * D_MODEL];
__device__ __half g_hh   [NTOK * D_MODEL];
__device__ __half g_ffh  [NTOK * D_FF];
__device__ float  g_tmp  [NTOK * D_MODEL];     // attn_proj, then ffn2 out
__device__ float  g_h    [NTOK * D_MODEL];     // LN1 output (fp32 residual)

// =======================================================================
// PTX helpers (plain sm_103-compatible: mma.sync / ldmatrix / cp.async)
// =======================================================================
__device__ __forceinline__ uint32_t smem_u32(const void* p) {
    uint32_t a;
    asm("{ .reg .u64 t; cvta.to.shared.u64 t, %1; cvt.u32.u64 %0, t; }"
        : "=r"(a) : "l"(p));
    return a;
}

__device__ __forceinline__ void mma16816(float* d, const uint32_t* a, const uint32_t* b) {
    asm volatile(
        "mma.sync.aligned.m16n8k16.row.col.f32.f16.f16.f32 "
        "{%0,%1,%2,%3}, {%4,%5,%6,%7}, {%8,%9}, {%0,%1,%2,%3};"
        : "+f"(d[0]), "+f"(d[1]), "+f"(d[2]), "+f"(d[3])
        : "r"(a[0]), "r"(a[1]), "r"(a[2]), "r"(a[3]), "r"(b[0]), "r"(b[1]));
}

#define LDMX4(r0, r1, r2, r3, addr)                                         \
    asm volatile("ldmatrix.sync.aligned.m8n8.x4.shared.b16 "                \
                 "{%0,%1,%2,%3}, [%4];"                                     \
                 : "=r"(r0), "=r"(r1), "=r"(r2), "=r"(r3) : "r"(addr))

#define LDMX4T(r0, r1, r2, r3, addr)                                        \
    asm volatile("ldmatrix.sync.aligned.m8n8.x4.trans.shared.b16 "          \
                 "{%0,%1,%2,%3}, [%4];"                                     \
                 : "=r"(r0), "=r"(r1), "=r"(r2), "=r"(r3) : "r"(addr))

#define CP_ASYNC16(saddr, gaddr)                                            \
    asm volatile("cp.async.cg.shared.global [%0], [%1], 16;"                \
                 :: "r"(saddr), "l"(gaddr) : "memory")
#define CP_COMMIT() asm volatile("cp.async.commit_group;" ::: "memory")
#define CP_WAIT(n)  asm volatile("cp.async.wait_group %0;" :: "n"(n) : "memory")

__device__ __forceinline__ uint32_t pack_h2(float lo, float hi) {
    __half2 h = __float22half2_rn(make_float2(lo, hi));
    return *(uint32_t*)&h;
}

// =======================================================================
// Fused fp32 -> fp16 conversion for all weight/act tensors in ONE launch.
// 2 float4-chunks per thread (ILP=2 vs latency-bound single chunk).
// Unit = 2^18 chunks; block (512 chunks) never straddles a unit boundary.
// =======================================================================
struct F2HArgs {
    const float4 *s0, *s1, *s2, *s3, *s4, *s5, *s6;
    uint2        *d0, *d1, *d2, *d3, *d4, *d5, *d6;
    const float *bq, *bk, *bv;
    float *bqkv;
};

__global__ __launch_bounds__(256)
void f2h_all(F2HArgs a)
{
    const int i = blockIdx.x * 512 + threadIdx.x;    // chunk 0 of this thread
    const int unit = i >> 18;
    const float4* s; uint2* d; int off;
    if      (unit <  4) { s = a.s0; d = a.d0; off = i;              }
    else if (unit == 4) { s = a.s1; d = a.d1; off = i - (4  << 18); }
    else if (unit == 5) { s = a.s2; d = a.d2; off = i - (5  << 18); }
    else if (unit == 6) { s = a.s3; d = a.d3; off = i - (6  << 18); }
    else if (unit == 7) { s = a.s4; d = a.d4; off = i - (7  << 18); }
    else if (unit < 12) { s = a.s5; d = a.d5; off = i - (8  << 18); }
    else                { s = a.s6; d = a.d6; off = i - (12 << 18); }

    const float4 v0 = s[off];
    const float4 v1 = s[off + 256];
    uint2 o0, o1;
    o0.x = pack_h2(v0.x, v0.y);  o0.y = pack_h2(v0.z, v0.w);
    o1.x = pack_h2(v1.x, v1.y);  o1.y = pack_h2(v1.z, v1.w);
    d[off]       = o0;
    d[off + 256] = o1;

    if (blockIdx.x == 0) {
#pragma unroll
        for (int r = 0; r < 4; r++) {
            const int c = threadIdx.x + r * 256;
            a.bqkv[c]        = a.bq[c];
            a.bqkv[c + 1024] = a.bk[c];
            a.bqkv[c + 2048] = a.bv[c];
        }
    }
}

// =======================================================================
// fp16 HMMA GEMM (R13 config, measured 475.9us total):
// CTA 128x128, BK=64, 128 threads = 4 warps (2Mx2N), warp tile 64x64.
// 3-stage cp.async pipeline (ONE __syncthreads per 64-K tile) + register
// double-buffered fragments rotating over 4 k-steps.
// SMEM rows padded to 72 halfs (144B): ldmatrix conflict-free. 2 CTAs/SM.
// =======================================================================
#define LDSH   72
#define GSTG   3
#define TILE_B (128 * LDSH * 2)           // 18432 B per matrix per stage
#define GSMEM  (2 * GSTG * TILE_B)        // 110592 B

template <bool RELU, bool HALF_OUT>
__global__ __launch_bounds__(128, 2)
void gemm_h(const __half* __restrict__ A, const __half* __restrict__ W,
            const float* __restrict__ bias, void* __restrict__ Cout,
            int M, int N, int K)
{
    extern __shared__ __align__(16) char dsm[];
    const uint32_t smemA = smem_u32(dsm);
    const uint32_t smemW = smemA + GSTG * TILE_B;

    const int tid  = threadIdx.x;
    const int wid  = tid >> 5;
    const int lane = tid & 31;
    const int wm   = wid >> 1;         // 2 -> 64 M-rows each
    const int wn   = wid & 1;          // 2 -> 64 N-cols each
    const int g    = lane >> 2;
    const int t4   = lane & 3;

    const int bm = blockIdx.y * 128;
    const int bn = blockIdx.x * 128;

    float acc[4][8][4];
#pragma unroll
    for (int i = 0; i < 4; i++)
#pragma unroll
        for (int j = 0; j < 8; j++)
#pragma unroll
            for (int c = 0; c < 4; c++) acc[i][j][c] = 0.f;

    // cp.async: 1024 16B-chunks per matrix per stage (128 rows x 8), 8/thread
#define ISSUE_G(t, s)                                                           \
    do {                                                                        \
        const uint32_t sa = smemA + (s) * TILE_B;                               \
        const uint32_t sw = smemW + (s) * TILE_B;                               \
        _Pragma("unroll")                                                       \
        for (int sl = 0; sl < 8; sl++) {                                        \
            const int idx = tid + sl * 128;                                     \
            const int row = idx >> 3, c16 = idx & 7;                            \
            CP_ASYNC16(sa + (uint32_t)((row * LDSH + c16 * 8) * 2),             \
                       A + (size_t)(bm + row) * K + (t) * 64 + c16 * 8);        \
        }                                                                       \
        _Pragma("unroll")                                                       \
        for (int sl = 0; sl < 8; sl++) {                                        \
            const int idx = tid + sl * 128;                                     \
            const int row = idx >> 3, c16 = idx & 7;                            \
            CP_ASYNC16(sw + (uint32_t)((row * LDSH + c16 * 8) * 2),             \
                       W + (size_t)(bn + row) * K + (t) * 64 + c16 * 8);        \
        }                                                                       \
    } while (0)

    // ldmatrix byte offsets within one stage
    const int r7   = lane & 7;
    const int rsel = (lane >> 3) & 1;
    const int hsel = lane >> 4;
    const uint32_t offA0 = (uint32_t)((wm * 64 + r7 + rsel * 8) * (LDSH * 2) + hsel * 16);
    const uint32_t offB0 = (uint32_t)((wn * 64 + r7 + hsel * 8) * (LDSH * 2) + rsel * 16);

    // fragment register double buffers
    uint32_t af0[4][4], bf0[8][2], af1[4][4], bf1[8][2];

#define LOAD_FRAG(af, bf, stage, ks)                                            \
    do {                                                                        \
        const uint32_t ab_ = smemA + (uint32_t)((stage) * TILE_B) + offA0 + (ks) * 32; \
        const uint32_t bb_ = smemW + (uint32_t)((stage) * TILE_B) + offB0 + (ks) * 32; \
        _Pragma("unroll")                                                       \
        for (int i = 0; i < 4; i++)                                             \
            LDMX4(af[i][0], af[i][1], af[i][2], af[i][3],                       \
                  ab_ + (uint32_t)(i * 16 * LDSH * 2));                         \
        _Pragma("unroll")                                                       \
        for (int jp = 0; jp < 4; jp++)                                          \
            LDMX4(bf[2 * jp][0], bf[2 * jp][1], bf[2 * jp + 1][0], bf[2 * jp + 1][1], \
                  bb_ + (uint32_t)(jp * 16 * LDSH * 2));                        \
    } while (0)

#define MMA_SET(af, bf)                                                         \
    do {                                                                        \
        _Pragma("unroll")                                                       \
        for (int i = 0; i < 4; i++)                                             \
            _Pragma("unroll")                                                   \
            for (int j = 0; j < 8; j++)                                         \
                mma16816(acc[i][j], af[i], bf[j]);                              \
    } while (0)

    const int NT = K / 64;

    // prologue: stages 0,1 in flight; stage 0 confirmed; frag(0,ks0) resident
    ISSUE_G(0, 0); CP_COMMIT();
    ISSUE_G(1, 1); CP_COMMIT();
    CP_WAIT(1);
    __syncthreads();
    LOAD_FRAG(af0, bf0, 0, 0);

    for (int t = 0; t < NT; ++t) {
        const int st = t % 3;
        // write stage t+2 into buffer (t+2)%3 = (t-1)%3 (freed by prev sync)
        if (t + 2 < NT) ISSUE_G(t + 2, (t + 2) % 3);
        CP_COMMIT();                       // always commit (empty in tail)

        LOAD_FRAG(af1, bf1, st, 1);
        MMA_SET(af0, bf0);                 // ks0
        LOAD_FRAG(af0, bf0, st, 2);
        MMA_SET(af1, bf1);                 // ks1
        LOAD_FRAG(af1, bf1, st, 3);
        MMA_SET(af0, bf0);                 // ks2
        if (t + 1 < NT) {
            CP_WAIT(1);                    // stages <= t+1 confirmed
            __syncthreads();               // all reads of buffer st done
            LOAD_FRAG(af0, bf0, (t + 1) % 3, 0);
        }
        MMA_SET(af1, bf1);                 // ks3
    }

    // ---- epilogue ----
#pragma unroll
    for (int j = 0; j < 8; j++) {
        const int col = bn + wn * 64 + j * 8 + t4 * 2;
        const float b0 = bias[col];
        const float b1 = bias[col + 1];
#pragma unroll
        for (int i = 0; i < 4; i++) {
            const int r0 = bm + wm * 64 + i * 16 + g;
            float v00 = acc[i][j][0] + b0, v01 = acc[i][j][1] + b1;
            float v10 = acc[i][j][2] + b0, v11 = acc[i][j][3] + b1;
            if (RELU) {
                v00 = fmaxf(v00, 0.f); v01 = fmaxf(v01, 0.f);
                v10 = fmaxf(v10, 0.f); v11 = fmaxf(v11, 0.f);
            }
            if (HALF_OUT) {
                __half* C = (__half*)Cout;
                *(__half2*)(C + (size_t)r0 * N + col)       = __float22half2_rn(make_float2(v00, v01));
                *(__half2*)(C + (size_t)(r0 + 8) * N + col) = __float22half2_rn(make_float2(v10, v11));
            } else {
                float* C = (float*)Cout;
                *(float2*)(C + (size_t)r0 * N + col)       = make_float2(v00, v01);
                *(float2*)(C + (size_t)(r0 + 8) * N + col) = make_float2(v10, v11);
            }
        }
    }
#undef ISSUE_G
#undef LOAD_FRAG
#undef MMA_SET
}

// =======================================================================
// fp16 HMMA flash attention over the fused QKV buffer (unchanged).
// =======================================================================
#define ATS 72

__global__ __launch_bounds__(256)
void flash16(const __half* __restrict__ QKV, __half* __restrict__ O)
{
    __shared__ __half Qs[128 * ATS];
    __shared__ __half Ks[2][64 * ATS];
    __shared__ __half Vs[2][64 * ATS];

    const int tid  = threadIdx.x;
    const int w    = tid >> 5;
    const int lane = tid & 31;
    const int g    = lane >> 2;
    const int t4   = lane & 3;
    const int bh   = blockIdx.y;
    const int b    = bh >> 4;
    const int h    = bh & 15;
    const int q0   = blockIdx.x * 128;
    const int m    = w * 16;

    const size_t baseQ = (size_t)b * SEQ * QKVS + (size_t)h * D_HEAD;
    const size_t baseK = baseQ + 1024;
    const size_t baseV = baseQ + 2048;
    const size_t baseO = (size_t)b * SEQ * D_MODEL + (size_t)h * D_HEAD;

    // ---- load Q tile (128 rows, scaled by 0.125) ----
    const __half2 sc = __float2half2_rn(0.125f);
#pragma unroll
    for (int s = 0; s < 4; s++) {
        int slot = tid + s * 256;          // 0..1023
        int row  = slot >> 3;              // 0..127
        int c8   = (slot & 7) * 8;
        uint4 v = *(const uint4*)(QKV + baseQ + (size_t)(q0 + row) * QKVS + c8);
        __half2* hv = (__half2*)&v;
        hv[0] = __hmul2(hv[0], sc); hv[1] = __hmul2(hv[1], sc);
        hv[2] = __hmul2(hv[2], sc); hv[3] = __hmul2(hv[3], sc);
        *(uint4*)&Qs[row * ATS + c8] = v;
    }
    __syncthreads();

    const int r7   = lane & 7;
    const int rsel = (lane >> 3) & 1;
    const int hsel = lane >> 4;

    uint32_t qf[4][4];
    {
        const uint32_t qb = smem_u32(Qs) +
            (uint32_t)((m + r7 + rsel * 8) * (ATS * 2) + hsel * 16);
#pragma unroll
        for (int ks = 0; ks < 4; ks++)
            LDMX4(qf[ks][0], qf[ks][1], qf[ks][2], qf[ks][3], qb + ks * 32);
    }

    const uint32_t offK0 = (uint32_t)((r7 + hsel * 8) * (ATS * 2) + rsel * 16);
    const uint32_t offV0 = (uint32_t)((rsel * 8 + r7) * (ATS * 2) + hsel * 16);
    const uint32_t kBase[2] = { smem_u32(Ks[0]), smem_u32(Ks[1]) };
    const uint32_t vBase[2] = { smem_u32(Vs[0]), smem_u32(Vs[1]) };

#define ISSUE_TILE(kt, buf)                                                     \
    do {                                                                        \
        _Pragma("unroll")                                                       \
        for (int s = 0; s < 2; s++) {                                           \
            int slot = tid + s * 256;      /* 0..511 */                         \
            int row  = slot >> 3;          /* 0..63 */                          \
            int c8   = (slot & 7) * 8;                                          \
            const size_t ro = (size_t)((kt) * 64 + row) * QKVS + c8;            \
            uint32_t so = (uint32_t)((row * ATS + c8) * 2);                     \
            CP_ASYNC16(kBase[buf] + so, QKV + baseK + ro);                      \
            CP_ASYNC16(vBase[buf] + so, QKV + baseV + ro);                      \
        }                                                                       \
        CP_COMMIT();                                                            \
    } while (0)

    float o[8][4];
#pragma unroll
    for (int j = 0; j < 8; j++)
#pragma unroll
        for (int c = 0; c < 4; c++) o[j][c] = 0.f;
    float m0 = -1e30f, m1 = -1e30f, l0 = 0.f, l1 = 0.f;

    ISSUE_TILE(0, 0);

    const int NKT = SEQ / 64;
    for (int kt = 0; kt < NKT; ++kt) {
        const int buf = kt & 1;
        if (kt + 1 < NKT) { ISSUE_TILE(kt + 1, buf ^ 1); CP_WAIT(1); }
        else              { CP_WAIT(0); }
        __syncthreads();

        // ---- S = (Q/8) K^T ----
        float s_[8][4];
#pragma unroll
        for (int j = 0; j < 8; j++)
#pragma unroll
            for (int c = 0; c < 4; c++) s_[j][c] = 0.f;

        const uint32_t kb = kBase[buf] + offK0;
#pragma unroll
        for (int ks = 0; ks < 4; ks++) {
            uint32_t bfk[8][2];
#pragma unroll
            for (int jp = 0; jp < 4; jp++)
                LDMX4(bfk[2 * jp][0], bfk[2 * jp][1], bfk[2 * jp + 1][0], bfk[2 * jp + 1][1],
                      kb + (uint32_t)(jp * 16 * ATS * 2 + ks * 32));
#pragma unroll
            for (int j = 0; j < 8; j++)
                mma16816(s_[j], qf[ks], bfk[j]);
        }

        // ---- online softmax ----
        float mx0 = -1e30f, mx1 = -1e30f;
#pragma unroll
        for (int j = 0; j < 8; j++) {
            mx0 = fmaxf(mx0, fmaxf(s_[j][0], s_[j][1]));
            mx1 = fmaxf(mx1, fmaxf(s_[j][2], s_[j][3]));
        }
        mx0 = fmaxf(mx0, __shfl_xor_sync(0xffffffffu, mx0, 1));
        mx0 = fmaxf(mx0, __shfl_xor_sync(0xffffffffu, mx0, 2));
        mx1 = fmaxf(mx1, __shfl_xor_sync(0xffffffffu, mx1, 1));
        mx1 = fmaxf(mx1, __shfl_xor_sync(0xffffffffu, mx1, 2));

        const float nm0 = fmaxf(m0, mx0);
        const float nm1 = fmaxf(m1, mx1);
        const float cr0 = __expf(m0 - nm0);
        const float cr1 = __expf(m1 - nm1);
        m0 = nm0; m1 = nm1;

        float ps0 = 0.f, ps1 = 0.f;
#pragma unroll
        for (int j = 0; j < 8; j++) {
            s_[j][0] = __expf(s_[j][0] - m0);
            s_[j][1] = __expf(s_[j][1] - m0);
            s_[j][2] = __expf(s_[j][2] - m1);
            s_[j][3] = __expf(s_[j][3] - m1);
            ps0 += s_[j][0] + s_[j][1];
            ps1 += s_[j][2] + s_[j][3];
        }
        ps0 += __shfl_xor_sync(0xffffffffu, ps0, 1);
        ps0 += __shfl_xor_sync(0xffffffffu, ps0, 2);
        ps1 += __shfl_xor_sync(0xffffffffu, ps1, 1);
        ps1 += __shfl_xor_sync(0xffffffffu, ps1, 2);
        l0 = l0 * cr0 + ps0;
        l1 = l1 * cr1 + ps1;

#pragma unroll
        for (int j = 0; j < 8; j++) {
            o[j][0] *= cr0; o[j][1] *= cr0;
            o[j][2] *= cr1; o[j][3] *= cr1;
        }

        // ---- O += P V ----
        const uint32_t vb = vBase[buf] + offV0;
#pragma unroll
        for (int ks = 0; ks < 4; ks++) {
            uint32_t pa[4];
            pa[0] = pack_h2(s_[2 * ks][0],     s_[2 * ks][1]);
            pa[1] = pack_h2(s_[2 * ks][2],     s_[2 * ks][3]);
            pa[2] = pack_h2(s_[2 * ks + 1][0], s_[2 * ks + 1][1]);
            pa[3] = pack_h2(s_[2 * ks + 1][2], s_[2 * ks + 1][3]);

            uint32_t bfv[8][2];
#pragma unroll
            for (int jp = 0; jp < 4; jp++)
                LDMX4T(bfv[2 * jp][0], bfv[2 * jp][1], bfv[2 * jp + 1][0], bfv[2 * jp + 1][1],
                       vb + (uint32_t)(ks * 16 * ATS * 2 + jp * 32));
#pragma unroll
            for (int j = 0; j < 8; j++)
                mma16816(o[j], pa, bfv[j]);
        }
        __syncthreads();
    }

    // ---- finalize + store (half) ----
    const float inv0 = 1.f / l0;
    const float inv1 = 1.f / l1;
    const int row0 = q0 + m + g;
    const int row1 = row0 + 8;
#pragma unroll
    for (int j = 0; j < 8; j++) {
        const int col = j * 8 + t4 * 2;
        *(__half2*)(O + baseO + (size_t)row0 * D_MODEL + col) =
            __float22half2_rn(make_float2(o[j][0] * inv0, o[j][1] * inv0));
        *(__half2*)(O + baseO + (size_t)row1 * D_MODEL + col) =
            __float22half2_rn(make_float2(o[j][2] * inv1, o[j][3] * inv1));
    }
#undef ISSUE_TILE
}

// =======================================================================
// Fused residual add + LayerNorm (float4-vectorized); optional half out.
// One block (256 threads) per row; each thread owns 4 consecutive floats.
// =======================================================================
__device__ __forceinline__ float block_sum(float v, float* red)
{
    for (int o = 16; o; o >>= 1) v += __shfl_down_sync(0xffffffffu, v, o);
    if ((threadIdx.x & 31) == 0) red[threadIdx.x >> 5] = v;
    __syncthreads();
    if (threadIdx.x < 8) {
        v = red[threadIdx.x];
        for (int o = 4; o; o >>= 1) v += __shfl_down_sync(0xffu, v, o);
        if (threadIdx.x == 0) red[0] = v;
    }
    __syncthreads();
    float r = red[0];
    __syncthreads();
    return r;
}

template <bool WRITE_HALF>
__global__ __launch_bounds__(256)
void add_ln_kernel(const float* __restrict__ X,
                   const float* __restrict__ Y,
                   const float* __restrict__ g,
                   const float* __restrict__ be,
                   float* __restrict__ out,
                   __half* __restrict__ outh)
{
    __shared__ float red[8];
    const int row = blockIdx.x;
    const int tid = threadIdx.x;
    const int c   = tid * 4;

    const float4 xv = *(const float4*)(X + (size_t)row * D_MODEL + c);
    const float4 yv = *(const float4*)(Y + (size_t)row * D_MODEL + c);

    float4 v;
    v.x = xv.x + yv.x; v.y = xv.y + yv.y;
    v.z = xv.z + yv.z; v.w = xv.w + yv.w;

    float mu = block_sum(v.x + v.y + v.z + v.w, red) * (1.f / D_MODEL);

    float dx = v.x - mu, dy = v.y - mu, dz = v.z - mu, dw = v.w - mu;
    float var = block_sum(dx * dx + dy * dy + dz * dz + dw * dw, red) * (1.f / D_MODEL);
    float rstd = rsqrtf(var + EPS);

    const float4 gv = *(const float4*)(g + c);
    const float4 bv = *(const float4*)(be + c);
    float4 r;
    r.x = dx * rstd * gv.x + bv.x;
    r.y = dy * rstd * gv.y + bv.y;
    r.z = dz * rstd * gv.z + bv.z;
    r.w = dw * rstd * gv.w + bv.w;

    *(float4*)(out + (size_t)row * D_MODEL + c) = r;
    if (WRITE_HALF) {
        uint2 hv;
        hv.x = pack_h2(r.x, r.y);
        hv.y = pack_h2(r.z, r.w);
        *(uint2*)(outh + (size_t)row * D_MODEL + c) = hv;
    }
}

// =======================================================================
// kernel_launch
// input order: x, Wq, bq, Wk, bk, Wv, bv, Wo, bo, W1, b1, W2, b2, g1, be1, g2, be2
// =======================================================================
extern "C" void kernel_launch(void* const* d_in, const int* in_sizes, int n_in,
                              void* d_out, int out_size)
{
    const float* x   = (const float*)d_in[0];
    const float* Wq  = (const float*)d_in[1];
    const float* bq  = (const float*)d_in[2];
    const float* Wk  = (const float*)d_in[3];
    const float* bk  = (const float*)d_in[4];
    const float* Wv  = (const float*)d_in[5];
    const float* bv  = (const float*)d_in[6];
    const float* Wo  = (const float*)d_in[7];
    const float* bo  = (const float*)d_in[8];
    const float* W1  = (const float*)d_in[9];
    const float* b1  = (const float*)d_in[10];
    const float* W2  = (const float*)d_in[11];
    const float* b2  = (const float*)d_in[12];
    const float* g1  = (const float*)d_in[13];
    const float* be1 = (const float*)d_in[14];
    const float* g2  = (const float*)d_in[15];
    const float* be2 = (const float*)d_in[16];
    float* out = (float*)d_out;

    __half *xh, *Wqkvh, *Woh, *W1h, *W2h, *qkvh, *atth, *hh, *ffh;
    float *bqkv, *tmp, *h;
    cudaGetSymbolAddress((void**)&xh,    g_xh);
    cudaGetSymbolAddress((void**)&Wqkvh, g_Wqkvh);
    cudaGetSymbolAddress((void**)&bqkv,  g_bqkv);
    cudaGetSymbolAddress((void**)&Woh,   g_Woh);
    cudaGetSymbolAddress((void**)&W1h,   g_W1h);
    cudaGetSymbolAddress((void**)&W2h,   g_W2h);
    cudaGetSymbolAddress((void**)&qkvh,  g_qkvh);
    cudaGetSymbolAddress((void**)&atth,  g_atth);
    cudaGetSymbolAddress((void**)&hh,    g_hh);
    cudaGetSymbolAddress((void**)&ffh,   g_ffh);
    cudaGetSymbolAddress((void**)&tmp,   g_tmp);
    cudaGetSymbolAddress((void**)&h,     g_h);

    cudaFuncSetAttribute(gemm_h<false, true >, cudaFuncAttributeMaxDynamicSharedMemorySize, GSMEM);
    cudaFuncSetAttribute(gemm_h<false, false>, cudaFuncAttributeMaxDynamicSharedMemorySize, GSMEM);
    cudaFuncSetAttribute(gemm_h<true,  true >, cudaFuncAttributeMaxDynamicSharedMemorySize, GSMEM);

    // ---- fused conversions + bias concat (single launch, 2 chunks/thread) ----
    F2HArgs fa;
    fa.s0 = (const float4*)x;  fa.d0 = (uint2*)xh;
    fa.s1 = (const float4*)Wq; fa.d1 = (uint2*)Wqkvh;                       // rows 0..1023
    fa.s2 = (const float4*)Wk; fa.d2 = (uint2*)(Wqkvh + 1024 * D_MODEL);    // rows 1024..
    fa.s3 = (const float4*)Wv; fa.d3 = (uint2*)(Wqkvh + 2048 * D_MODEL);    // rows 2048..
    fa.s4 = (const float4*)Wo; fa.d4 = (uint2*)Woh;
    fa.s5 = (const float4*)W1; fa.d5 = (uint2*)W1h;
    fa.s6 = (const float4*)W2; fa.d6 = (uint2*)W2h;
    fa.bq = bq; fa.bk = bk; fa.bv = bv; fa.bqkv = bqkv;
    f2h_all<<<(16 << 18) / 512, 256>>>(fa);

    const dim3 gQKV(QKVS / 128,    NTOK / 128);   // (24, 32)
    const dim3 gDxD(D_MODEL / 128, NTOK / 128);   // (8, 32)
    const dim3 gFF1(D_FF / 128,    NTOK / 128);   // (32, 32)

    // fused QKV projection -> half [NTOK][3072]
    gemm_h<false, true><<<gQKV, 128, GSMEM>>>(xh, Wqkvh, bqkv, qkvh, NTOK, QKVS, D_MODEL);

    // attention -> half
    flash16<<<dim3(SEQ / 128, BATCH * NHEAD), 256>>>(qkvh, atth);

    // output projection (fp32 out) + LN1 (fp32 + half out)
    gemm_h<false, false><<<gDxD, 128, GSMEM>>>(atth, Woh, bo, tmp, NTOK, D_MODEL, D_MODEL);
    add_ln_kernel<true><<<NTOK, 256>>>(x, tmp, g1, be1, h, hh);

    // FFN
    gemm_h<true,  true ><<<gFF1, 128, GSMEM>>>(hh,  W1h, b1, ffh, NTOK, D_FF, D_MODEL);
    gemm_h<false, false><<<gDxD, 128, GSMEM>>>(ffh, W2h, b2, tmp, NTOK, D_MODEL, D_FF);

    // LN2 -> output
    add_ln_kernel<false><<<NTOK, 256>>>(h, tmp, g2, be2, out, nullptr);
}